// round 7
// baseline (speedup 1.0000x reference)
#include <cuda_runtime.h>
#include <cuda_bf16.h>
#include <cuda_fp16.h>
#include <math.h>
#include <stdint.h>

#define N_NODES 50000
#define N_EDGES 800000
#define ET      (N_EDGES + N_NODES)
#define DIN     256
#define HEADS   8
#define CH      32
#define DOUT    256
#define CAP     128
#define NEG_SLOPE 0.2f
#define LN_EPS  1e-5f

#define MT      391                 // ceil(50000/128)
#define MROWS   (MT * 128)          // 50048 padded rows

// ---------------- static device scratch ----------------
__device__ __half g_hf[(size_t)N_NODES * DOUT];        // fp16 h (message gathers)
__device__ float g_asrc[N_NODES * HEADS];
__device__ float g_adst[N_NODES * HEADS];
__device__ int   g_cnt[N_NODES];
__device__ int   g_csr_src[(size_t)N_NODES * CAP];
__device__ __nv_bfloat16 g_Ahi[(size_t)MROWS * DIN];   // 25.6 MB row-major [m][k]
__device__ __nv_bfloat16 g_Alo[(size_t)MROWS * DIN];
__device__ __nv_bfloat16 g_Bhi[DOUT * DIN];            // W transposed: [n][k]
__device__ __nv_bfloat16 g_Blo[DOUT * DIN];

// ---------------- helpers ----------------
__device__ __forceinline__ uint32_t smem_u32(const void* p) {
    uint32_t a;
    asm("{ .reg .u64 t; cvta.to.shared.u64 t, %1; cvt.u32.u64 %0, t; }" : "=r"(a) : "l"(p));
    return a;
}
__device__ __forceinline__ void cp_async16(uint32_t s, const void* g) {
    asm volatile("cp.async.cg.shared.global [%0], [%1], 16;" :: "r"(s), "l"(g));
}
#define CP_COMMIT() asm volatile("cp.async.commit_group;" ::: "memory")
#define CP_WAIT0()  asm volatile("cp.async.wait_group 0;" ::: "memory")
#define CP_WAIT1()  asm volatile("cp.async.wait_group 1;" ::: "memory")

__device__ __forceinline__ void mma16816(float* d, const uint32_t* a, const uint32_t* b) {
    asm volatile(
        "mma.sync.aligned.m16n8k16.row.col.f32.bf16.bf16.f32 "
        "{%0,%1,%2,%3}, {%4,%5,%6,%7}, {%8,%9}, {%0,%1,%2,%3};"
        : "+f"(d[0]), "+f"(d[1]), "+f"(d[2]), "+f"(d[3])
        : "r"(a[0]), "r"(a[1]), "r"(a[2]), "r"(a[3]), "r"(b[0]), "r"(b[1]));
}

// ---------------- kernel 0: clear counters ----------------
__global__ void zero_kernel() {
    int t = blockIdx.x * blockDim.x + threadIdx.x;
    if (t < N_NODES) g_cnt[t] = 0;
}

// ---------------- prepass A: x -> bf16 hi/lo row-major ----------------
__global__ __launch_bounds__(256) void prepA_kernel(const float* __restrict__ x) {
    int u = blockIdx.x * blockDim.x + threadIdx.x;     // one per 8 elems
    if (u >= MROWS * (DIN / 8)) return;
    int k8  = (u & 31) * 8;
    int row = u >> 5;

    float v[8];
    if (row < N_NODES) {
        const float4* p = (const float4*)(x + (size_t)row * DIN + k8);
        float4 a = p[0], b = p[1];
        v[0]=a.x; v[1]=a.y; v[2]=a.z; v[3]=a.w; v[4]=b.x; v[5]=b.y; v[6]=b.z; v[7]=b.w;
    } else {
#pragma unroll
        for (int j = 0; j < 8; j++) v[j] = 0.f;
    }
    __nv_bfloat16 hi[8], lo[8];
#pragma unroll
    for (int j = 0; j < 8; j++) {
        hi[j] = __float2bfloat16(v[j]);
        lo[j] = __float2bfloat16(v[j] - __bfloat162float(hi[j]));
    }
    *(uint4*)(g_Ahi + (size_t)row * DIN + k8) = *(uint4*)hi;
    *(uint4*)(g_Alo + (size_t)row * DIN + k8) = *(uint4*)lo;
}

// ---------------- prepass W: W[k][n] -> Bt[n][k] bf16 hi/lo ----------------
__global__ __launch_bounds__(256) void prepW_kernel(const float* __restrict__ W) {
    int u = blockIdx.x * blockDim.x + threadIdx.x;
    if (u >= DOUT * (DIN / 8)) return;
    int k8 = (u & 31) * 8;
    int n  = u >> 5;
    __nv_bfloat16 hi[8], lo[8];
#pragma unroll
    for (int j = 0; j < 8; j++) {
        float w = W[(size_t)(k8 + j) * DOUT + n];
        hi[j] = __float2bfloat16(w);
        lo[j] = __float2bfloat16(w - __bfloat162float(hi[j]));
    }
    *(uint4*)(g_Bhi + (size_t)n * DIN + k8) = *(uint4*)hi;
    *(uint4*)(g_Blo + (size_t)n * DIN + k8) = *(uint4*)lo;
}

// ---------------- HMMA GEMM: h = x @ W, bf16 hi/lo 3-term, fused attn dots ----------------
#define BK        32
#define ROWSTRIDE 40
#define TILE_B    (128 * ROWSTRIDE * 2)     // 10240 bytes
#define STAGE_B   (4 * TILE_B)              // 40960
#define SMEM_B    (2 * STAGE_B)             // 81920

__global__ __launch_bounds__(256, 2) void gemm_mma_kernel(const float* __restrict__ att_src,
                                                          const float* __restrict__ att_dst) {
    extern __shared__ char sm[];
    uint32_t sbase = smem_u32(sm);

    int tid  = threadIdx.x;
    int wid  = tid >> 5;
    int lane = tid & 31;
    int wm   = wid >> 2;          // 0..1
    int wn   = wid & 3;           // 0..3
    int g    = lane >> 2;         // 0..7
    int t2   = (lane & 3) * 2;    // 0,2,4,6

    int m0 = blockIdx.x * 128;
    int n0 = blockIdx.y * 128;

    const __nv_bfloat16* gsrc[4] = {
        g_Ahi + (size_t)m0 * DIN, g_Alo + (size_t)m0 * DIN,
        g_Bhi + (size_t)n0 * DIN, g_Blo + (size_t)n0 * DIN };

    float acc[4][4][4];
#pragma unroll
    for (int i = 0; i < 4; i++)
#pragma unroll
        for (int j = 0; j < 4; j++)
#pragma unroll
            for (int q = 0; q < 4; q++) acc[i][j][q] = 0.f;

    auto load_stage = [&](int kb, int buf) {
        uint32_t sb = sbase + buf * STAGE_B;
        int k0 = kb * BK;
#pragma unroll
        for (int tile = 0; tile < 4; tile++) {
#pragma unroll
            for (int p = 0; p < 2; p++) {
                int i   = tid + p * 256;
                int row = i >> 2, q = i & 3;
                uint32_t soff = sb + tile * TILE_B + (row * ROWSTRIDE + q * 8) * 2;
                cp_async16(soff, gsrc[tile] + (size_t)row * DIN + k0 + q * 8);
            }
        }
        CP_COMMIT();
    };

    load_stage(0, 0);

    for (int kb = 0; kb < 8; kb++) {
        int buf = kb & 1;
        if (kb < 7) load_stage(kb + 1, buf ^ 1);
        if (kb < 7) CP_WAIT1(); else CP_WAIT0();
        __syncthreads();

        const __nv_bfloat16* sAhi = (const __nv_bfloat16*)(sm + buf * STAGE_B);
        const __nv_bfloat16* sAlo = sAhi + 128 * ROWSTRIDE;
        const __nv_bfloat16* sBhi = sAlo + 128 * ROWSTRIDE;
        const __nv_bfloat16* sBlo = sBhi + 128 * ROWSTRIDE;

#pragma unroll
        for (int ks = 0; ks < 2; ks++) {
            int kk = ks * 16 + t2;
            uint32_t bf[4][2][2];
#pragma unroll
            for (int j = 0; j < 4; j++) {
                int nr = wn * 32 + j * 8 + g;
                bf[j][0][0] = *(const uint32_t*)(sBhi + nr * ROWSTRIDE + kk);
                bf[j][0][1] = *(const uint32_t*)(sBhi + nr * ROWSTRIDE + kk + 8);
                bf[j][1][0] = *(const uint32_t*)(sBlo + nr * ROWSTRIDE + kk);
                bf[j][1][1] = *(const uint32_t*)(sBlo + nr * ROWSTRIDE + kk + 8);
            }
#pragma unroll
            for (int i = 0; i < 4; i++) {
                int mr = wm * 64 + i * 16 + g;
                uint32_t ah[4], al[4];
                ah[0] = *(const uint32_t*)(sAhi + mr * ROWSTRIDE + kk);
                ah[1] = *(const uint32_t*)(sAhi + (mr + 8) * ROWSTRIDE + kk);
                ah[2] = *(const uint32_t*)(sAhi + mr * ROWSTRIDE + kk + 8);
                ah[3] = *(const uint32_t*)(sAhi + (mr + 8) * ROWSTRIDE + kk + 8);
                al[0] = *(const uint32_t*)(sAlo + mr * ROWSTRIDE + kk);
                al[1] = *(const uint32_t*)(sAlo + (mr + 8) * ROWSTRIDE + kk);
                al[2] = *(const uint32_t*)(sAlo + mr * ROWSTRIDE + kk + 8);
                al[3] = *(const uint32_t*)(sAlo + (mr + 8) * ROWSTRIDE + kk + 8);
#pragma unroll
                for (int j = 0; j < 4; j++) {
                    mma16816(acc[i][j], ah, bf[j][0]);   // hi @ W_hi
                    mma16816(acc[i][j], ah, bf[j][1]);   // hi @ W_lo
                    mma16816(acc[i][j], al, bf[j][0]);   // lo @ W_hi
                }
            }
        }
        __syncthreads();
    }

    // ---- epilogue 1: fp16 h stores ----
#pragma unroll
    for (int i = 0; i < 4; i++) {
        int m = m0 + wm * 64 + i * 16 + g;
#pragma unroll
        for (int j = 0; j < 4; j++) {
            int col = n0 + wn * 32 + j * 8 + t2;
            if (m < N_NODES)
                *(__half2*)(g_hf + (size_t)m * DOUT + col) =
                    __floats2half2_rn(acc[i][j][0], acc[i][j][1]);
            if (m + 8 < N_NODES)
                *(__half2*)(g_hf + (size_t)(m + 8) * DOUT + col) =
                    __floats2half2_rn(acc[i][j][2], acc[i][j][3]);
        }
    }

    // ---- epilogue 2: exact attention dots from fp32 fragments ----
    // head owned by this warp: cols n0+wn*32 .. +31 == head (blockIdx.y*4 + wn), fully covered.
    int head = blockIdx.y * 4 + wn;
    float aS[4][2], aD[4][2];
#pragma unroll
    for (int j = 0; j < 4; j++) {
        int c = j * 8 + t2;
        aS[j][0] = att_src[head * CH + c];
        aS[j][1] = att_src[head * CH + c + 1];
        aD[j][0] = att_dst[head * CH + c];
        aD[j][1] = att_dst[head * CH + c + 1];
    }
    float ps[8], pd[8];
#pragma unroll
    for (int q = 0; q < 8; q++) { ps[q] = 0.f; pd[q] = 0.f; }
#pragma unroll
    for (int i = 0; i < 4; i++)
#pragma unroll
        for (int j = 0; j < 4; j++) {
            ps[2 * i]     += acc[i][j][0] * aS[j][0] + acc[i][j][1] * aS[j][1];
            ps[2 * i + 1] += acc[i][j][2] * aS[j][0] + acc[i][j][3] * aS[j][1];
            pd[2 * i]     += acc[i][j][0] * aD[j][0] + acc[i][j][1] * aD[j][1];
            pd[2 * i + 1] += acc[i][j][2] * aD[j][0] + acc[i][j][3] * aD[j][1];
        }
    // reduce over the 4 lanes of each quad (same rows, different cols)
#pragma unroll
    for (int o = 1; o <= 2; o <<= 1) {
#pragma unroll
        for (int q = 0; q < 8; q++) {
            ps[q] += __shfl_xor_sync(0xFFFFFFFFu, ps[q], o);
            pd[q] += __shfl_xor_sync(0xFFFFFFFFu, pd[q], o);
        }
    }
    if ((lane & 3) == 0) {
#pragma unroll
        for (int i = 0; i < 4; i++) {
            int m = m0 + wm * 64 + i * 16 + g;
            if (m < N_NODES) {
                g_asrc[m * HEADS + head] = ps[2 * i];
                g_adst[m * HEADS + head] = pd[2 * i];
            }
            if (m + 8 < N_NODES) {
                g_asrc[(m + 8) * HEADS + head] = ps[2 * i + 1];
                g_adst[(m + 8) * HEADS + head] = pd[2 * i + 1];
            }
        }
    }
}

// ---------------- bucket edges by dst ----------------
__global__ void scatter_kernel(const int* __restrict__ ei) {
    int t = blockIdx.x * blockDim.x + threadIdx.x;
    if (t >= ET) return;
    int s, d;
    if (t < N_EDGES) {
        s = ei[t];
        d = ei[N_EDGES + t];
    } else {
        s = d = t - N_EDGES;
    }
    if ((unsigned)s >= N_NODES || (unsigned)d >= N_NODES) return;
    int pos = atomicAdd(&g_cnt[d], 1);
    if (pos < CAP) g_csr_src[(size_t)d * CAP + pos] = s;
}

// ---------------- warp-per-dst softmax-aggregate (fp16 gathers, 2x unroll) + bias + LN + ReLU ----------------
__global__ __launch_bounds__(256) void aggr_kernel(const float* __restrict__ bias,
                                                   const float* __restrict__ gamma,
                                                   const float* __restrict__ beta,
                                                   float* __restrict__ out) {
    int warp = (blockIdx.x * blockDim.x + threadIdx.x) >> 5;
    int lane = threadIdx.x & 31;
    if (warp >= N_NODES) return;
    int d    = warp;
    int head = lane >> 2;
    int base = lane * 8;

    float adv = g_adst[d * HEADS + head];
    int cnt = g_cnt[d];
    if (cnt > CAP) cnt = CAP;

    float acc[8];
#pragma unroll
    for (int q = 0; q < 8; q++) acc[q] = 0.f;
    float S = 0.f;

    const int* lst = g_csr_src + (size_t)d * CAP;
    int i = 0;
    for (; i + 2 <= cnt; i += 2) {
        int s0 = lst[i], s1 = lst[i + 1];
        float a0 = g_asrc[s0 * HEADS + head];
        float a1 = g_asrc[s1 * HEADS + head];
        uint4 hv0 = *(const uint4*)(g_hf + (size_t)s0 * DOUT + base);
        uint4 hv1 = *(const uint4*)(g_hf + (size_t)s1 * DOUT + base);
        float e0 = a0 + adv; e0 = (e0 > 0.f) ? e0 : NEG_SLOPE * e0;
        float e1 = a1 + adv; e1 = (e1 > 0.f) ? e1 : NEG_SLOPE * e1;
        float x0 = __expf(e0), x1 = __expf(e1);
        S += x0 + x1;
        float2 f;
        f = __half22float2(*(__half2*)&hv0.x); acc[0] += x0 * f.x; acc[1] += x0 * f.y;
        f = __half22float2(*(__half2*)&hv0.y); acc[2] += x0 * f.x; acc[3] += x0 * f.y;
        f = __half22float2(*(__half2*)&hv0.z); acc[4] += x0 * f.x; acc[5] += x0 * f.y;
        f = __half22float2(*(__half2*)&hv0.w); acc[6] += x0 * f.x; acc[7] += x0 * f.y;
        f = __half22float2(*(__half2*)&hv1.x); acc[0] += x1 * f.x; acc[1] += x1 * f.y;
        f = __half22float2(*(__half2*)&hv1.y); acc[2] += x1 * f.x; acc[3] += x1 * f.y;
        f = __half22float2(*(__half2*)&hv1.z); acc[4] += x1 * f.x; acc[5] += x1 * f.y;
        f = __half22float2(*(__half2*)&hv1.w); acc[6] += x1 * f.x; acc[7] += x1 * f.y;
    }
    if (i < cnt) {
        int s0 = lst[i];
        float e0 = g_asrc[s0 * HEADS + head] + adv;
        e0 = (e0 > 0.f) ? e0 : NEG_SLOPE * e0;
        float x0 = __expf(e0);
        S += x0;
        uint4 hv0 = *(const uint4*)(g_hf + (size_t)s0 * DOUT + base);
        float2 f;
        f = __half22float2(*(__half2*)&hv0.x); acc[0] += x0 * f.x; acc[1] += x0 * f.y;
        f = __half22float2(*(__half2*)&hv0.y); acc[2] += x0 * f.x; acc[3] += x0 * f.y;
        f = __half22float2(*(__half2*)&hv0.z); acc[4] += x0 * f.x; acc[5] += x0 * f.y;
        f = __half22float2(*(__half2*)&hv0.w); acc[6] += x0 * f.x; acc[7] += x0 * f.y;
    }
    float inv = 1.f / S;

    float v[8];
#pragma unroll
    for (int q = 0; q < 8; q++) v[q] = acc[q] * inv + bias[base + q];

    float sum = 0.f, sq = 0.f;
#pragma unroll
    for (int k = 0; k < 8; k++) { sum += v[k]; sq += v[k] * v[k]; }
#pragma unroll
    for (int o = 16; o > 0; o >>= 1) {
        sum += __shfl_xor_sync(0xFFFFFFFFu, sum, o);
        sq  += __shfl_xor_sync(0xFFFFFFFFu, sq,  o);
    }
    float mu   = sum * (1.f / 256.f);
    float var  = sq * (1.f / 256.f) - mu * mu;
    float rstd = rsqrtf(var + LN_EPS);

    float r[8];
#pragma unroll
    for (int k = 0; k < 8; k++) {
        float tt = (v[k] - mu) * rstd * gamma[base + k] + beta[base + k];
        r[k] = (tt > 0.f) ? tt : 0.f;
    }
    float4* op = (float4*)(out + (size_t)d * DOUT + base);
    op[0] = make_float4(r[0], r[1], r[2], r[3]);
    op[1] = make_float4(r[4], r[5], r[6], r[7]);
}

// ---------------- launch ----------------
extern "C" void kernel_launch(void* const* d_in, const int* in_sizes, int n_in,
                              void* d_out, int out_size) {
    const float* x       = (const float*)d_in[0];
    const int*   ei      = (const int*)d_in[1];
    const float* W       = (const float*)d_in[2];
    const float* att_src = (const float*)d_in[3];
    const float* att_dst = (const float*)d_in[4];
    const float* bias    = (const float*)d_in[5];
    const float* gamma   = (const float*)d_in[6];
    const float* beta    = (const float*)d_in[7];
    float*       out     = (float*)d_out;

    static bool attr_set = false;
    if (!attr_set) {
        cudaFuncSetAttribute(gemm_mma_kernel, cudaFuncAttributeMaxDynamicSharedMemorySize, SMEM_B);
        attr_set = true;
    }

    zero_kernel<<<(N_NODES + 255) / 256, 256>>>();

    prepA_kernel<<<(MROWS * 32 + 255) / 256, 256>>>(x);
    prepW_kernel<<<(DOUT * 32 + 255) / 256, 256>>>(W);

    dim3 ggrid(MT, 2);
    gemm_mma_kernel<<<ggrid, 256, SMEM_B>>>(att_src, att_dst);

    scatter_kernel<<<(ET + 255) / 256, 256>>>(ei);

    aggr_kernel<<<(N_NODES * 32 + 255) / 256, 256>>>(bias, gamma, beta, out);
}